// round 15
// baseline (speedup 1.0000x reference)
#include <cuda_runtime.h>
#include <cuda_fp16.h>
#include <cstdint>

// ============================================================
// LSTM cell, sm_103 legacy-HMMA path (tcgen05 unavailable in this
// PTX target). GEMM M=4096, N=8192, K=4096 fp16->fp32, fused epilogue.
// R15: transpose pre-pass ELIMINATED. W converted in-layout to
// gate-interleaved row-major W16[k][n'=u*4+gate] (pure streaming),
// GEMM B fragments loaded with ldmatrix.x2.trans. GEMM config
// (tiles/stages/occupancy/supertile) unchanged from the 796us best.
// ============================================================

#define BROWS 4096
#define DIN   2048
#define UNITS 2048
#define KTOT  4096
#define NTOT  8192

#define BM 128
#define BN 128
#define BK 64
#define NITER (KTOT / BK)    // 64
#define STAGES 3

// A smem rows: 64 halfs (128B) + 16B pad = 144B
#define ROWB 144
#define ATILE (BM * ROWB)              // 18432 per stage
// B smem rows: 64 k-rows of 256B (128 n-halfs) + 16B pad = 272B
#define ROWBB 272
#define BTILE (BK * ROWBB)             // 17408 per stage
#define SM_BOFF (STAGES * ATILE)       // 55296
#define SMEM_TOTAL (SM_BOFF + STAGES * BTILE)   // 107520 (2 CTAs/SM)

// -------- device scratch --------
__device__ __half g_Z [(size_t)BROWS * KTOT];    // 32 MB, z fp16 K-major
__device__ __half g_Wn[(size_t)KTOT  * NTOT];    // 64 MB, [k][n'=u*4+gate]

// -------- helpers --------
__device__ __forceinline__ uint32_t smem_u32(const void* p) {
    uint32_t a;
    asm("{ .reg .u64 t; cvta.to.shared.u64 t, %1; cvt.u32.u64 %0, t; }" : "=r"(a) : "l"(p));
    return a;
}
__device__ __forceinline__ void cp16(uint32_t dst, const void* src) {
    asm volatile("cp.async.cg.shared.global [%0], [%1], 16;" :: "r"(dst), "l"(src));
}
#define CP_COMMIT() asm volatile("cp.async.commit_group;" ::: "memory")
#define CP_WAIT(n)  asm volatile("cp.async.wait_group %0;" :: "n"(n) : "memory")

__device__ __forceinline__ float sigf(float x)      { return 1.f / (1.f + __expf(-x)); }
__device__ __forceinline__ float tanhfast(float x)  { return 1.f - 2.f / (__expf(2.f * x) + 1.f); }

// ============================================================
// K1: pack z = [x | h] -> fp16, 8 elements per thread, vectorized
// ============================================================
__global__ void pack_z_kernel(const float* __restrict__ x, const float* __restrict__ h) {
    int i = blockIdx.x * blockDim.x + threadIdx.x;     // over 4096*4096/8
    int row = i >> 9;
    int col = (i & 511) << 3;
    const float* src = (col < DIN) ? x + (size_t)row * DIN + col
                                   : h + (size_t)row * UNITS + (col - DIN);
    float4 a = reinterpret_cast<const float4*>(src)[0];
    float4 b = reinterpret_cast<const float4*>(src)[1];
    __half2 p0 = __floats2half2_rn(a.x, a.y);
    __half2 p1 = __floats2half2_rn(a.z, a.w);
    __half2 p2 = __floats2half2_rn(b.x, b.y);
    __half2 p3 = __floats2half2_rn(b.z, b.w);
    uint4 o;
    o.x = *reinterpret_cast<uint32_t*>(&p0);
    o.y = *reinterpret_cast<uint32_t*>(&p1);
    o.z = *reinterpret_cast<uint32_t*>(&p2);
    o.w = *reinterpret_cast<uint32_t*>(&p3);
    reinterpret_cast<uint4*>(g_Z)[i] = o;
}

// ============================================================
// K2: interleave W -> W16[k][n'=u*4+gate], fp16. NO transpose:
// pure streaming, register-only. Each thread: one (k, u-quad):
// 4x float4 coalesced reads (one per gate) -> one 32B coalesced write.
// ============================================================
__global__ void interleave_w_kernel(const float* __restrict__ Wf, const float* __restrict__ Wi,
                                    const float* __restrict__ Wc, const float* __restrict__ Wo) {
    int i = blockIdx.x * blockDim.x + threadIdx.x;     // over 4096 * 512
    int k  = i >> 9;            // 0..4095
    int ug = i & 511;           // u-quad index; u = 4*ug
    size_t src = (size_t)k * UNITS + (ug << 2);
    float4 f = *reinterpret_cast<const float4*>(&Wf[src]);
    float4 g = *reinterpret_cast<const float4*>(&Wi[src]);
    float4 c = *reinterpret_cast<const float4*>(&Wc[src]);
    float4 o = *reinterpret_cast<const float4*>(&Wo[src]);

    // output halfs, j-th quad: (f_j, i_j, c_j, o_j) at n' = (4ug+j)*4
    __half2 h0 = __floats2half2_rn(f.x, g.x), h1 = __floats2half2_rn(c.x, o.x);
    __half2 h2 = __floats2half2_rn(f.y, g.y), h3 = __floats2half2_rn(c.y, o.y);
    __half2 h4 = __floats2half2_rn(f.z, g.z), h5 = __floats2half2_rn(c.z, o.z);
    __half2 h6 = __floats2half2_rn(f.w, g.w), h7 = __floats2half2_rn(c.w, o.w);
    uint4 o0, o1;
    o0.x = *reinterpret_cast<uint32_t*>(&h0);
    o0.y = *reinterpret_cast<uint32_t*>(&h1);
    o0.z = *reinterpret_cast<uint32_t*>(&h2);
    o0.w = *reinterpret_cast<uint32_t*>(&h3);
    o1.x = *reinterpret_cast<uint32_t*>(&h4);
    o1.y = *reinterpret_cast<uint32_t*>(&h5);
    o1.z = *reinterpret_cast<uint32_t*>(&h6);
    o1.w = *reinterpret_cast<uint32_t*>(&h7);
    __half* dst = &g_Wn[(size_t)k * NTOT + ((size_t)ug << 4)];
    reinterpret_cast<uint4*>(dst)[0] = o0;
    reinterpret_cast<uint4*>(dst)[1] = o1;
}

// ============================================================
// K3: GEMM (BK=64, 3 stages, 2 CTA/SM) + fused LSTM epilogue.
// A path unchanged; B loaded row-major (k x n) + ldmatrix.x2.trans.
// ============================================================
__device__ __forceinline__ void load_stage(uint32_t sb, int tid, int m0, int n0,
                                           int s, int buf) {
    const int k0 = s * BK;
    #pragma unroll
    for (int j = 0; j < 4; ++j) {               // A: 1024 chunks of 16B
        int c   = tid + j * 256;
        int row = c >> 3, kc = c & 7;
        uint32_t d = sb + buf * ATILE + row * ROWB + kc * 16;
        cp16(d, &g_Z[(size_t)(m0 + row) * KTOT + k0 + kc * 8]);
    }
    #pragma unroll
    for (int j = 0; j < 4; ++j) {               // B: 64 k-rows x 16 chunks
        int c   = tid + j * 256;
        int row = c >> 4, kc = c & 15;
        uint32_t d = sb + SM_BOFF + buf * BTILE + row * ROWBB + kc * 16;
        cp16(d, &g_Wn[(size_t)(k0 + row) * NTOT + n0 + kc * 8]);
    }
}

__device__ __forceinline__ void compute_stage(uint32_t aBase, uint32_t bBase,
                                              int warp_m, int warp_n, int lane,
                                              float acc[4][4][4]) {
    #pragma unroll
    for (int ks = 0; ks < 4; ++ks) {            // four k16 steps per BK=64
        uint32_t a[4][4];
        uint32_t b[4][2];
        #pragma unroll
        for (int mi = 0; mi < 4; ++mi) {
            uint32_t addr = aBase + (uint32_t)(warp_m * 64 + mi * 16 + (lane & 15)) * ROWB
                          + ks * 32 + ((lane >> 4) << 4);
            asm volatile("ldmatrix.sync.aligned.m8n8.x4.shared.b16 {%0,%1,%2,%3}, [%4];"
                : "=r"(a[mi][0]), "=r"(a[mi][1]), "=r"(a[mi][2]), "=r"(a[mi][3])
                : "r"(addr));
        }
        // B: row-major (k x n) smem + trans ldmatrix.
        // lanes 0-7 -> k rows ks*16+0..7 (tile0 -> reg0 = k0-7),
        // lanes 8-15 -> k rows ks*16+8..15 (tile1 -> reg1 = k8-15).
        #pragma unroll
        for (int ni = 0; ni < 4; ++ni) {
            uint32_t addr = bBase + (uint32_t)(ks * 16 + (lane & 15)) * ROWBB
                          + (warp_n * 32 + ni * 8) * 2;
            asm volatile("ldmatrix.sync.aligned.m8n8.x2.trans.shared.b16 {%0,%1}, [%2];"
                : "=r"(b[ni][0]), "=r"(b[ni][1])
                : "r"(addr));
        }
        #pragma unroll
        for (int mi = 0; mi < 4; ++mi)
            #pragma unroll
            for (int ni = 0; ni < 4; ++ni)
                asm("mma.sync.aligned.m16n8k16.row.col.f32.f16.f16.f32 "
                    "{%0,%1,%2,%3}, {%4,%5,%6,%7}, {%8,%9}, {%0,%1,%2,%3};"
                    : "+f"(acc[mi][ni][0]), "+f"(acc[mi][ni][1]),
                      "+f"(acc[mi][ni][2]), "+f"(acc[mi][ni][3])
                    : "r"(a[mi][0]), "r"(a[mi][1]), "r"(a[mi][2]), "r"(a[mi][3]),
                      "r"(b[ni][0]), "r"(b[ni][1]));
    }
}

__global__ void __launch_bounds__(256, 2) gemm_lstm_kernel(
    const float* __restrict__ cin,
    const float* __restrict__ bfv, const float* __restrict__ biv,
    const float* __restrict__ bcv, const float* __restrict__ bov,
    float* __restrict__ out) {
    extern __shared__ char smem[];
    const uint32_t sb = smem_u32(smem);
    const int tid = threadIdx.x, wid = tid >> 5, lane = tid & 31;
    const int warp_m = wid & 1;      // 2 warp rows of 64
    const int warp_n = wid >> 1;     // 4 warp cols of 32

    // L2-friendly supertile mapping: groups of 8 M-tiles per N sweep
    const int NTN = NTOT / BN;       // 64
    const int GM = 8;
    int bid = blockIdx.x;
    int g = bid / (GM * NTN), r = bid % (GM * NTN);
    int mt = g * GM + (r % GM);
    int nt = r / GM;
    int m0 = mt * BM, n0 = nt * BN;

    float acc[4][4][4];
    #pragma unroll
    for (int mi = 0; mi < 4; ++mi)
        #pragma unroll
        for (int ni = 0; ni < 4; ++ni)
            #pragma unroll
            for (int q = 0; q < 4; ++q) acc[mi][ni][q] = 0.f;

    load_stage(sb, tid, m0, n0, 0, 0); CP_COMMIT();
    load_stage(sb, tid, m0, n0, 1, 1); CP_COMMIT();

    for (int i = 0; i < NITER; ++i) {
        if (i + 2 < NITER) {
            CP_WAIT(1);
            __syncthreads();
            load_stage(sb, tid, m0, n0, i + 2, (i + 2) % STAGES);
            CP_COMMIT();
        } else if (i + 2 == NITER) {
            CP_WAIT(1);
            __syncthreads();
        } else {
            CP_WAIT(0);
            __syncthreads();
        }
        int buf = i % STAGES;
        compute_stage(sb + buf * ATILE, sb + SM_BOFF + buf * BTILE,
                      warp_m, warp_n, lane, acc);
    }

    // ---------------- fused LSTM epilogue ----------------
    // Cols gate-interleaved: n = u*4 + gate. Thread col pair is (f,i)
    // [even lane] or (c,o) [odd lane] of unit u; one bfly-1 shuffle
    // completes the quad: even lane -> row r, odd lane -> row r+8.
    #pragma unroll
    for (int mi = 0; mi < 4; ++mi) {
        #pragma unroll
        for (int ni = 0; ni < 4; ++ni) {
            int rbase = m0 + warp_m * 64 + mi * 16 + (lane >> 2);
            int u = ((n0 + warp_n * 32 + ni * 8) >> 2) + ((lane & 3) >> 1);
            float d0 = acc[mi][ni][0], d1 = acc[mi][ni][1];
            float d2 = acc[mi][ni][2], d3 = acc[mi][ni][3];
            float s0 = (lane & 1) ? d0 : d2;
            float s1 = (lane & 1) ? d1 : d3;
            float t0 = __shfl_xor_sync(0xffffffffu, s0, 1);
            float t1 = __shfl_xor_sync(0xffffffffu, s1, 1);
            float fg, ig, cg, og; int row;
            if (!(lane & 1)) { fg = d0; ig = d1; cg = t0; og = t1; row = rbase; }
            else             { fg = t0; ig = t1; cg = d2; og = d3; row = rbase + 8; }
            fg += __ldg(&bfv[u]); ig += __ldg(&biv[u]);
            cg += __ldg(&bcv[u]); og += __ldg(&bov[u]);
            float ft = sigf(fg), it = sigf(ig);
            float gt = tanhfast(cg), ot = sigf(og);
            size_t idx = (size_t)row * UNITS + u;
            float nc = ft * __ldg(&cin[idx]) + it * gt;
            float nh = ot * tanhfast(nc);
            out[idx] = nh;                                   // new_h
            out[(size_t)BROWS * UNITS + idx] = nc;           // new_c
        }
    }
}

// ============================================================
// kernel_launch — pack_z on stream0 || interleave_w on s2, join, GEMM.
// ============================================================
extern "C" void kernel_launch(void* const* d_in, const int* in_sizes, int n_in,
                              void* d_out, int out_size) {
    const float* x  = (const float*)d_in[0];
    const float* h  = (const float*)d_in[1];
    const float* c  = (const float*)d_in[2];
    const float* Wf = (const float*)d_in[3];
    const float* bf = (const float*)d_in[4];
    const float* Wi = (const float*)d_in[5];
    const float* bi = (const float*)d_in[6];
    const float* Wc = (const float*)d_in[7];
    const float* bc = (const float*)d_in[8];
    const float* Wo = (const float*)d_in[9];
    const float* bo = (const float*)d_in[10];
    float* out = (float*)d_out;

    static cudaStream_t s2 = nullptr;
    static cudaEvent_t evFork = nullptr, evJoin = nullptr;
    static bool inited = false;
    if (!inited) {
        cudaStreamCreateWithFlags(&s2, cudaStreamNonBlocking);
        cudaEventCreateWithFlags(&evFork, cudaEventDisableTiming);
        cudaEventCreateWithFlags(&evJoin, cudaEventDisableTiming);
        cudaFuncSetAttribute(gemm_lstm_kernel,
                             cudaFuncAttributeMaxDynamicSharedMemorySize, SMEM_TOTAL);
        inited = true;
    }

    // fork to s2
    cudaEventRecord(evFork, 0);
    cudaStreamWaitEvent(s2, evFork, 0);

    // s2: interleave W (96 MB streaming)
    interleave_w_kernel<<<(KTOT * (UNITS / 4)) / 256, 256, 0, s2>>>(Wf, Wi, Wc, Wo);

    // stream0: pack z (96 MB streaming)
    pack_z_kernel<<<(BROWS * KTOT / 8) / 256, 256>>>(x, h);

    // join s2 back to stream0
    cudaEventRecord(evJoin, s2);
    cudaStreamWaitEvent(0, evJoin, 0);

    int grid = (BROWS / BM) * (NTOT / BN);   // 2048
    gemm_lstm_kernel<<<grid, 256, SMEM_TOTAL>>>(c, bf, bi, bc, bo, out);
}

// round 16
// speedup vs baseline: 1.0536x; 1.0536x over previous
#include <cuda_runtime.h>
#include <cuda_fp16.h>
#include <cstdint>

// ============================================================
// LSTM cell, sm_103 legacy-HMMA path (tcgen05 unavailable in this
// PTX target). GEMM M=4096, N=8192, K=4096 fp16->fp32, fused epilogue.
// FINAL = verified-best configuration (R11, 796.0us):
//   K1: pack z=[x|h] -> fp16 (vectorized, 8 elem/thread)
//   K2: W -> Wt[n][k] fp16, gate-interleaved n = u*4 + gate (pad 65)
//   K3: GEMM 128x128x64, warp 64x32, 3-stage cp.async, 2 CTA/SM,
//       non-volatile MMA, fused LSTM epilogue via lane-pair shuffle.
// Established plateau: GEMM 744.8us (tensor=60.9%), pre-pass ~50us
// (DRAM-bound, 288MB). Structural alternatives all regressed
// (1-CTA/SM, persistent CTAs, x4-B, trans-B, chunk-split).
// ============================================================

#define BROWS 4096
#define DIN   2048
#define UNITS 2048
#define KTOT  4096
#define NTOT  8192

#define BM 128
#define BN 128
#define BK 64
#define NITER (KTOT / BK)    // 64
#define STAGES 3

// SMEM rows: 64 halfs (128B) + 16B pad = 144B
#define ROWB 144
#define ATILE (BM * ROWB)              // 18432 per stage
#define BTILE (BN * ROWB)              // 18432
#define SM_BOFF (STAGES * ATILE)       // 55296
#define SMEM_TOTAL (STAGES * (ATILE + BTILE))   // 110592 (2 CTAs/SM)

// -------- device scratch --------
__device__ __half g_Z [(size_t)BROWS * KTOT];    // 32 MB
__device__ __half g_Wt[(size_t)NTOT  * KTOT];    // 64 MB, n = u*4+gate

// -------- helpers --------
__device__ __forceinline__ uint32_t smem_u32(const void* p) {
    uint32_t a;
    asm("{ .reg .u64 t; cvta.to.shared.u64 t, %1; cvt.u32.u64 %0, t; }" : "=r"(a) : "l"(p));
    return a;
}
__device__ __forceinline__ void cp16(uint32_t dst, const void* src) {
    asm volatile("cp.async.cg.shared.global [%0], [%1], 16;" :: "r"(dst), "l"(src));
}
#define CP_COMMIT() asm volatile("cp.async.commit_group;" ::: "memory")
#define CP_WAIT(n)  asm volatile("cp.async.wait_group %0;" :: "n"(n) : "memory")

__device__ __forceinline__ float sigf(float x)      { return 1.f / (1.f + __expf(-x)); }
__device__ __forceinline__ float tanhfast(float x)  { return 1.f - 2.f / (__expf(2.f * x) + 1.f); }

// ============================================================
// K1: pack z = [x | h] -> fp16, 8 elements per thread, vectorized
// ============================================================
__global__ void pack_z_kernel(const float* __restrict__ x, const float* __restrict__ h) {
    int i = blockIdx.x * blockDim.x + threadIdx.x;     // over 4096*4096/8
    int row = i >> 9;
    int col = (i & 511) << 3;
    const float* src = (col < DIN) ? x + (size_t)row * DIN + col
                                   : h + (size_t)row * UNITS + (col - DIN);
    float4 a = reinterpret_cast<const float4*>(src)[0];
    float4 b = reinterpret_cast<const float4*>(src)[1];
    __half2 p0 = __floats2half2_rn(a.x, a.y);
    __half2 p1 = __floats2half2_rn(a.z, a.w);
    __half2 p2 = __floats2half2_rn(b.x, b.y);
    __half2 p3 = __floats2half2_rn(b.z, b.w);
    uint4 o;
    o.x = *reinterpret_cast<uint32_t*>(&p0);
    o.y = *reinterpret_cast<uint32_t*>(&p1);
    o.z = *reinterpret_cast<uint32_t*>(&p2);
    o.w = *reinterpret_cast<uint32_t*>(&p3);
    reinterpret_cast<uint4*>(g_Z)[i] = o;
}

// ============================================================
// K2: Wt[n][k] = W_gate[k][u] fp16, n = u*4 + gate (K contiguous)
// 64x64 tiles, float4 loads, uint4 stores, pad 65 (2-way conflicts).
// grid (64,32,4), block (16,16)
// ============================================================
__global__ void transpose_w_kernel(const float* __restrict__ Wf, const float* __restrict__ Wi,
                                   const float* __restrict__ Wc, const float* __restrict__ Wo) {
    __shared__ float t[64][65];
    int k0 = blockIdx.x * 64;
    int u0 = blockIdx.y * 64;
    int gz = blockIdx.z;
    const float* W = (gz == 0) ? Wf : (gz == 1) ? Wi : (gz == 2) ? Wc : Wo;
    int tx = threadIdx.x, ty = threadIdx.y;
    int tid = ty * 16 + tx;

    #pragma unroll
    for (int r = ty; r < 64; r += 16) {
        float4 v = *reinterpret_cast<const float4*>(&W[(size_t)(k0 + r) * UNITS + u0 + 4 * tx]);
        t[r][4 * tx + 0] = v.x;
        t[r][4 * tx + 1] = v.y;
        t[r][4 * tx + 2] = v.z;
        t[r][4 * tx + 3] = v.w;
    }
    __syncthreads();

    #pragma unroll
    for (int it = 0; it < 2; ++it) {
        int idx = tid + it * 256;
        int uu = idx >> 3;
        int kc = idx & 7;
        int n = (u0 + uu) * 4 + gz;
        __half2 hp[4];
        #pragma unroll
        for (int q = 0; q < 4; ++q)
            hp[q] = __floats2half2_rn(t[kc * 8 + 2 * q][uu], t[kc * 8 + 2 * q + 1][uu]);
        uint4 o;
        o.x = *reinterpret_cast<uint32_t*>(&hp[0]);
        o.y = *reinterpret_cast<uint32_t*>(&hp[1]);
        o.z = *reinterpret_cast<uint32_t*>(&hp[2]);
        o.w = *reinterpret_cast<uint32_t*>(&hp[3]);
        *reinterpret_cast<uint4*>(&g_Wt[(size_t)n * KTOT + k0 + kc * 8]) = o;
    }
}

// ============================================================
// K3: GEMM (BK=64, 3 stages, 2 CTA/SM) + fused LSTM epilogue [FROZEN]
// ============================================================
__device__ __forceinline__ void load_stage(uint32_t sb, int tid, int m0, int n0,
                                           int s, int buf) {
    const int k0 = s * BK;
    #pragma unroll
    for (int j = 0; j < 4; ++j) {               // A: 1024 chunks of 16B
        int c   = tid + j * 256;
        int row = c >> 3, kc = c & 7;
        uint32_t d = sb + buf * ATILE + row * ROWB + kc * 16;
        cp16(d, &g_Z[(size_t)(m0 + row) * KTOT + k0 + kc * 8]);
    }
    #pragma unroll
    for (int j = 0; j < 4; ++j) {               // B: 1024 chunks of 16B
        int c   = tid + j * 256;
        int row = c >> 3, kc = c & 7;
        uint32_t d = sb + SM_BOFF + buf * BTILE + row * ROWB + kc * 16;
        cp16(d, &g_Wt[(size_t)(n0 + row) * KTOT + k0 + kc * 8]);
    }
}

__device__ __forceinline__ void compute_stage(uint32_t aBase, uint32_t bBase,
                                              int warp_m, int warp_n, int lane,
                                              float acc[4][4][4]) {
    #pragma unroll
    for (int ks = 0; ks < 4; ++ks) {            // four k16 steps per BK=64
        uint32_t a[4][4];
        uint32_t b[4][2];
        #pragma unroll
        for (int mi = 0; mi < 4; ++mi) {
            uint32_t addr = aBase + (uint32_t)(warp_m * 64 + mi * 16 + (lane & 15)) * ROWB
                          + ks * 32 + ((lane >> 4) << 4);
            asm volatile("ldmatrix.sync.aligned.m8n8.x4.shared.b16 {%0,%1,%2,%3}, [%4];"
                : "=r"(a[mi][0]), "=r"(a[mi][1]), "=r"(a[mi][2]), "=r"(a[mi][3])
                : "r"(addr));
        }
        int l16 = lane & 15;
        #pragma unroll
        for (int ni = 0; ni < 4; ++ni) {
            uint32_t addr = bBase + (uint32_t)(warp_n * 32 + ni * 8 + (l16 & 7)) * ROWB
                          + ks * 32 + ((l16 >> 3) << 4);
            asm volatile("ldmatrix.sync.aligned.m8n8.x2.shared.b16 {%0,%1}, [%2];"
                : "=r"(b[ni][0]), "=r"(b[ni][1])
                : "r"(addr));
        }
        // non-volatile MMA (neutral vs volatile; kept from the 796us best)
        #pragma unroll
        for (int mi = 0; mi < 4; ++mi)
            #pragma unroll
            for (int ni = 0; ni < 4; ++ni)
                asm("mma.sync.aligned.m16n8k16.row.col.f32.f16.f16.f32 "
                    "{%0,%1,%2,%3}, {%4,%5,%6,%7}, {%8,%9}, {%0,%1,%2,%3};"
                    : "+f"(acc[mi][ni][0]), "+f"(acc[mi][ni][1]),
                      "+f"(acc[mi][ni][2]), "+f"(acc[mi][ni][3])
                    : "r"(a[mi][0]), "r"(a[mi][1]), "r"(a[mi][2]), "r"(a[mi][3]),
                      "r"(b[ni][0]), "r"(b[ni][1]));
    }
}

__global__ void __launch_bounds__(256, 2) gemm_lstm_kernel(
    const float* __restrict__ cin,
    const float* __restrict__ bfv, const float* __restrict__ biv,
    const float* __restrict__ bcv, const float* __restrict__ bov,
    float* __restrict__ out) {
    extern __shared__ char smem[];
    const uint32_t sb = smem_u32(smem);
    const int tid = threadIdx.x, wid = tid >> 5, lane = tid & 31;
    const int warp_m = wid & 1;      // 2 warp rows of 64
    const int warp_n = wid >> 1;     // 4 warp cols of 32

    // L2-friendly supertile mapping: groups of 8 M-tiles per N sweep
    const int NTN = NTOT / BN;       // 64
    const int GM = 8;
    int bid = blockIdx.x;
    int g = bid / (GM * NTN), r = bid % (GM * NTN);
    int mt = g * GM + (r % GM);
    int nt = r / GM;
    int m0 = mt * BM, n0 = nt * BN;

    float acc[4][4][4];
    #pragma unroll
    for (int mi = 0; mi < 4; ++mi)
        #pragma unroll
        for (int ni = 0; ni < 4; ++ni)
            #pragma unroll
            for (int q = 0; q < 4; ++q) acc[mi][ni][q] = 0.f;

    load_stage(sb, tid, m0, n0, 0, 0); CP_COMMIT();
    load_stage(sb, tid, m0, n0, 1, 1); CP_COMMIT();

    for (int i = 0; i < NITER; ++i) {
        if (i + 2 < NITER) {
            CP_WAIT(1);
            __syncthreads();
            load_stage(sb, tid, m0, n0, i + 2, (i + 2) % STAGES);
            CP_COMMIT();
        } else if (i + 2 == NITER) {
            CP_WAIT(1);
            __syncthreads();
        } else {
            CP_WAIT(0);
            __syncthreads();
        }
        int buf = i % STAGES;
        compute_stage(sb + buf * ATILE, sb + SM_BOFF + buf * BTILE,
                      warp_m, warp_n, lane, acc);
    }

    // ---------------- fused LSTM epilogue ----------------
    // Cols gate-interleaved: n = u*4 + gate. Thread col pair is (f,i)
    // [even lane] or (c,o) [odd lane] of unit u; one bfly-1 shuffle
    // completes the quad: even lane -> row r, odd lane -> row r+8.
    #pragma unroll
    for (int mi = 0; mi < 4; ++mi) {
        #pragma unroll
        for (int ni = 0; ni < 4; ++ni) {
            int rbase = m0 + warp_m * 64 + mi * 16 + (lane >> 2);
            int u = ((n0 + warp_n * 32 + ni * 8) >> 2) + ((lane & 3) >> 1);
            float d0 = acc[mi][ni][0], d1 = acc[mi][ni][1];
            float d2 = acc[mi][ni][2], d3 = acc[mi][ni][3];
            float s0 = (lane & 1) ? d0 : d2;
            float s1 = (lane & 1) ? d1 : d3;
            float t0 = __shfl_xor_sync(0xffffffffu, s0, 1);
            float t1 = __shfl_xor_sync(0xffffffffu, s1, 1);
            float fg, ig, cg, og; int row;
            if (!(lane & 1)) { fg = d0; ig = d1; cg = t0; og = t1; row = rbase; }
            else             { fg = t0; ig = t1; cg = d2; og = d3; row = rbase + 8; }
            fg += __ldg(&bfv[u]); ig += __ldg(&biv[u]);
            cg += __ldg(&bcv[u]); og += __ldg(&bov[u]);
            float ft = sigf(fg), it = sigf(ig);
            float gt = tanhfast(cg), ot = sigf(og);
            size_t idx = (size_t)row * UNITS + u;
            float nc = ft * __ldg(&cin[idx]) + it * gt;
            float nh = ot * tanhfast(nc);
            out[idx] = nh;                                   // new_h
            out[(size_t)BROWS * UNITS + idx] = nc;           // new_c
        }
    }
}

// ============================================================
// kernel_launch — K1 || K2 fork/join, then K3.
// ============================================================
extern "C" void kernel_launch(void* const* d_in, const int* in_sizes, int n_in,
                              void* d_out, int out_size) {
    const float* x  = (const float*)d_in[0];
    const float* h  = (const float*)d_in[1];
    const float* c  = (const float*)d_in[2];
    const float* Wf = (const float*)d_in[3];
    const float* bf = (const float*)d_in[4];
    const float* Wi = (const float*)d_in[5];
    const float* bi = (const float*)d_in[6];
    const float* Wc = (const float*)d_in[7];
    const float* bc = (const float*)d_in[8];
    const float* Wo = (const float*)d_in[9];
    const float* bo = (const float*)d_in[10];
    float* out = (float*)d_out;

    static cudaStream_t s2 = nullptr;
    static cudaEvent_t evFork = nullptr, evJoin = nullptr;
    static bool inited = false;
    if (!inited) {
        cudaStreamCreateWithFlags(&s2, cudaStreamNonBlocking);
        cudaEventCreateWithFlags(&evFork, cudaEventDisableTiming);
        cudaEventCreateWithFlags(&evJoin, cudaEventDisableTiming);
        cudaFuncSetAttribute(gemm_lstm_kernel,
                             cudaFuncAttributeMaxDynamicSharedMemorySize, SMEM_TOTAL);
        inited = true;
    }

    // fork: pack_z on main stream, transpose_w on s2 (independent)
    cudaEventRecord(evFork, 0);
    cudaStreamWaitEvent(s2, evFork, 0);

    pack_z_kernel<<<(BROWS * KTOT / 8) / 256, 256>>>(x, h);

    dim3 tg(KTOT / 64, UNITS / 64, 4);
    transpose_w_kernel<<<tg, dim3(16, 16), 0, s2>>>(Wf, Wi, Wc, Wo);

    // join back to main stream
    cudaEventRecord(evJoin, s2);
    cudaStreamWaitEvent(0, evJoin, 0);

    int grid = (BROWS / BM) * (NTOT / BN);   // 2048
    gemm_lstm_kernel<<<grid, 256, SMEM_TOTAL>>>(c, bf, bi, bc, bo, out);
}

// round 17
// speedup vs baseline: 1.0677x; 1.0134x over previous
#include <cuda_runtime.h>
#include <cuda_fp16.h>
#include <cstdint>

// ============================================================
// LSTM cell, sm_103 legacy-HMMA path (tcgen05 unavailable in this
// PTX target). GEMM M=4096, N=8192, K=4096 fp16->fp32, fused epilogue.
// R17 = R16 (verified 794us) with the pre-pass fork/join replaced by
// ONE fused kernel launch (pack blocks + transpose blocks in a single
// grid) -> no events, scheduler interleaves both DRAM-bound halves.
// GEMM untouched (FROZEN).
// ============================================================

#define BROWS 4096
#define DIN   2048
#define UNITS 2048
#define KTOT  4096
#define NTOT  8192

#define BM 128
#define BN 128
#define BK 64
#define NITER (KTOT / BK)    // 64
#define STAGES 3

// SMEM rows: 64 halfs (128B) + 16B pad = 144B
#define ROWB 144
#define ATILE (BM * ROWB)              // 18432 per stage
#define BTILE (BN * ROWB)              // 18432
#define SM_BOFF (STAGES * ATILE)       // 55296
#define SMEM_TOTAL (STAGES * (ATILE + BTILE))   // 110592 (2 CTAs/SM)

#define PACK_BLOCKS  8192              // 4096*4096/8 elems / 256 thr
#define TRANS_BLOCKS 8192              // 64 ktiles * 32 utiles * 4 gates

// -------- device scratch --------
__device__ __half g_Z [(size_t)BROWS * KTOT];    // 32 MB
__device__ __half g_Wt[(size_t)NTOT  * KTOT];    // 64 MB, n = u*4+gate

// -------- helpers --------
__device__ __forceinline__ uint32_t smem_u32(const void* p) {
    uint32_t a;
    asm("{ .reg .u64 t; cvta.to.shared.u64 t, %1; cvt.u32.u64 %0, t; }" : "=r"(a) : "l"(p));
    return a;
}
__device__ __forceinline__ void cp16(uint32_t dst, const void* src) {
    asm volatile("cp.async.cg.shared.global [%0], [%1], 16;" :: "r"(dst), "l"(src));
}
#define CP_COMMIT() asm volatile("cp.async.commit_group;" ::: "memory")
#define CP_WAIT(n)  asm volatile("cp.async.wait_group %0;" :: "n"(n) : "memory")

__device__ __forceinline__ float sigf(float x)      { return 1.f / (1.f + __expf(-x)); }
__device__ __forceinline__ float tanhfast(float x)  { return 1.f - 2.f / (__expf(2.f * x) + 1.f); }

// ============================================================
// K1 (fused pre-pass): blocks [0, PACK_BLOCKS) pack z = [x|h] -> fp16;
// blocks [PACK_BLOCKS, PACK_BLOCKS+TRANS_BLOCKS) transpose W ->
// Wt[n][k], n = u*4 + gate (pad-65 smem, 2-way conflicts).
// Both bodies are byte-identical to the verified split kernels.
// ============================================================
__global__ void __launch_bounds__(256) prepass_kernel(
    const float* __restrict__ x,  const float* __restrict__ h,
    const float* __restrict__ Wf, const float* __restrict__ Wi,
    const float* __restrict__ Wc, const float* __restrict__ Wo) {
    __shared__ float t[64][65];
    int tid = threadIdx.x;

    if (blockIdx.x < PACK_BLOCKS) {
        // ---- pack z ----
        int i = blockIdx.x * 256 + tid;            // over 4096*4096/8
        int row = i >> 9;
        int col = (i & 511) << 3;
        const float* src = (col < DIN) ? x + (size_t)row * DIN + col
                                       : h + (size_t)row * UNITS + (col - DIN);
        float4 a = reinterpret_cast<const float4*>(src)[0];
        float4 b = reinterpret_cast<const float4*>(src)[1];
        __half2 p0 = __floats2half2_rn(a.x, a.y);
        __half2 p1 = __floats2half2_rn(a.z, a.w);
        __half2 p2 = __floats2half2_rn(b.x, b.y);
        __half2 p3 = __floats2half2_rn(b.z, b.w);
        uint4 o;
        o.x = *reinterpret_cast<uint32_t*>(&p0);
        o.y = *reinterpret_cast<uint32_t*>(&p1);
        o.z = *reinterpret_cast<uint32_t*>(&p2);
        o.w = *reinterpret_cast<uint32_t*>(&p3);
        reinterpret_cast<uint4*>(g_Z)[i] = o;
        return;
    }

    // ---- transpose W ----
    int b  = blockIdx.x - PACK_BLOCKS;             // 0..8191
    int k0 = (b & 63) * 64;                        // 64 k-tiles (fastest)
    int u0 = ((b >> 6) & 31) * 64;                 // 32 u-tiles
    int gz = b >> 11;                              // 4 gates
    const float* W = (gz == 0) ? Wf : (gz == 1) ? Wi : (gz == 2) ? Wc : Wo;
    int tx = tid & 15, ty = tid >> 4;

    #pragma unroll
    for (int r = ty; r < 64; r += 16) {
        float4 v = *reinterpret_cast<const float4*>(&W[(size_t)(k0 + r) * UNITS + u0 + 4 * tx]);
        t[r][4 * tx + 0] = v.x;
        t[r][4 * tx + 1] = v.y;
        t[r][4 * tx + 2] = v.z;
        t[r][4 * tx + 3] = v.w;
    }
    __syncthreads();

    #pragma unroll
    for (int it = 0; it < 2; ++it) {
        int idx = tid + it * 256;
        int uu = idx >> 3;
        int kc = idx & 7;
        int n = (u0 + uu) * 4 + gz;
        __half2 hp[4];
        #pragma unroll
        for (int q = 0; q < 4; ++q)
            hp[q] = __floats2half2_rn(t[kc * 8 + 2 * q][uu], t[kc * 8 + 2 * q + 1][uu]);
        uint4 o;
        o.x = *reinterpret_cast<uint32_t*>(&hp[0]);
        o.y = *reinterpret_cast<uint32_t*>(&hp[1]);
        o.z = *reinterpret_cast<uint32_t*>(&hp[2]);
        o.w = *reinterpret_cast<uint32_t*>(&hp[3]);
        *reinterpret_cast<uint4*>(&g_Wt[(size_t)n * KTOT + k0 + kc * 8]) = o;
    }
}

// ============================================================
// K3: GEMM (BK=64, 3 stages, 2 CTA/SM) + fused LSTM epilogue [FROZEN]
// ============================================================
__device__ __forceinline__ void load_stage(uint32_t sb, int tid, int m0, int n0,
                                           int s, int buf) {
    const int k0 = s * BK;
    #pragma unroll
    for (int j = 0; j < 4; ++j) {               // A: 1024 chunks of 16B
        int c   = tid + j * 256;
        int row = c >> 3, kc = c & 7;
        uint32_t d = sb + buf * ATILE + row * ROWB + kc * 16;
        cp16(d, &g_Z[(size_t)(m0 + row) * KTOT + k0 + kc * 8]);
    }
    #pragma unroll
    for (int j = 0; j < 4; ++j) {               // B: 1024 chunks of 16B
        int c   = tid + j * 256;
        int row = c >> 3, kc = c & 7;
        uint32_t d = sb + SM_BOFF + buf * BTILE + row * ROWB + kc * 16;
        cp16(d, &g_Wt[(size_t)(n0 + row) * KTOT + k0 + kc * 8]);
    }
}

__device__ __forceinline__ void compute_stage(uint32_t aBase, uint32_t bBase,
                                              int warp_m, int warp_n, int lane,
                                              float acc[4][4][4]) {
    #pragma unroll
    for (int ks = 0; ks < 4; ++ks) {            // four k16 steps per BK=64
        uint32_t a[4][4];
        uint32_t b[4][2];
        #pragma unroll
        for (int mi = 0; mi < 4; ++mi) {
            uint32_t addr = aBase + (uint32_t)(warp_m * 64 + mi * 16 + (lane & 15)) * ROWB
                          + ks * 32 + ((lane >> 4) << 4);
            asm volatile("ldmatrix.sync.aligned.m8n8.x4.shared.b16 {%0,%1,%2,%3}, [%4];"
                : "=r"(a[mi][0]), "=r"(a[mi][1]), "=r"(a[mi][2]), "=r"(a[mi][3])
                : "r"(addr));
        }
        int l16 = lane & 15;
        #pragma unroll
        for (int ni = 0; ni < 4; ++ni) {
            uint32_t addr = bBase + (uint32_t)(warp_n * 32 + ni * 8 + (l16 & 7)) * ROWB
                          + ks * 32 + ((l16 >> 3) << 4);
            asm volatile("ldmatrix.sync.aligned.m8n8.x2.shared.b16 {%0,%1}, [%2];"
                : "=r"(b[ni][0]), "=r"(b[ni][1])
                : "r"(addr));
        }
        #pragma unroll
        for (int mi = 0; mi < 4; ++mi)
            #pragma unroll
            for (int ni = 0; ni < 4; ++ni)
                asm("mma.sync.aligned.m16n8k16.row.col.f32.f16.f16.f32 "
                    "{%0,%1,%2,%3}, {%4,%5,%6,%7}, {%8,%9}, {%0,%1,%2,%3};"
                    : "+f"(acc[mi][ni][0]), "+f"(acc[mi][ni][1]),
                      "+f"(acc[mi][ni][2]), "+f"(acc[mi][ni][3])
                    : "r"(a[mi][0]), "r"(a[mi][1]), "r"(a[mi][2]), "r"(a[mi][3]),
                      "r"(b[ni][0]), "r"(b[ni][1]));
    }
}

__global__ void __launch_bounds__(256, 2) gemm_lstm_kernel(
    const float* __restrict__ cin,
    const float* __restrict__ bfv, const float* __restrict__ biv,
    const float* __restrict__ bcv, const float* __restrict__ bov,
    float* __restrict__ out) {
    extern __shared__ char smem[];
    const uint32_t sb = smem_u32(smem);
    const int tid = threadIdx.x, wid = tid >> 5, lane = tid & 31;
    const int warp_m = wid & 1;      // 2 warp rows of 64
    const int warp_n = wid >> 1;     // 4 warp cols of 32

    // L2-friendly supertile mapping: groups of 8 M-tiles per N sweep
    const int NTN = NTOT / BN;       // 64
    const int GM = 8;
    int bid = blockIdx.x;
    int g = bid / (GM * NTN), r = bid % (GM * NTN);
    int mt = g * GM + (r % GM);
    int nt = r / GM;
    int m0 = mt * BM, n0 = nt * BN;

    float acc[4][4][4];
    #pragma unroll
    for (int mi = 0; mi < 4; ++mi)
        #pragma unroll
        for (int ni = 0; ni < 4; ++ni)
            #pragma unroll
            for (int q = 0; q < 4; ++q) acc[mi][ni][q] = 0.f;

    load_stage(sb, tid, m0, n0, 0, 0); CP_COMMIT();
    load_stage(sb, tid, m0, n0, 1, 1); CP_COMMIT();

    for (int i = 0; i < NITER; ++i) {
        if (i + 2 < NITER) {
            CP_WAIT(1);
            __syncthreads();
            load_stage(sb, tid, m0, n0, i + 2, (i + 2) % STAGES);
            CP_COMMIT();
        } else if (i + 2 == NITER) {
            CP_WAIT(1);
            __syncthreads();
        } else {
            CP_WAIT(0);
            __syncthreads();
        }
        int buf = i % STAGES;
        compute_stage(sb + buf * ATILE, sb + SM_BOFF + buf * BTILE,
                      warp_m, warp_n, lane, acc);
    }

    // ---------------- fused LSTM epilogue ----------------
    // Cols gate-interleaved: n = u*4 + gate. Thread col pair is (f,i)
    // [even lane] or (c,o) [odd lane] of unit u; one bfly-1 shuffle
    // completes the quad: even lane -> row r, odd lane -> row r+8.
    #pragma unroll
    for (int mi = 0; mi < 4; ++mi) {
        #pragma unroll
        for (int ni = 0; ni < 4; ++ni) {
            int rbase = m0 + warp_m * 64 + mi * 16 + (lane >> 2);
            int u = ((n0 + warp_n * 32 + ni * 8) >> 2) + ((lane & 3) >> 1);
            float d0 = acc[mi][ni][0], d1 = acc[mi][ni][1];
            float d2 = acc[mi][ni][2], d3 = acc[mi][ni][3];
            float s0 = (lane & 1) ? d0 : d2;
            float s1 = (lane & 1) ? d1 : d3;
            float t0 = __shfl_xor_sync(0xffffffffu, s0, 1);
            float t1 = __shfl_xor_sync(0xffffffffu, s1, 1);
            float fg, ig, cg, og; int row;
            if (!(lane & 1)) { fg = d0; ig = d1; cg = t0; og = t1; row = rbase; }
            else             { fg = t0; ig = t1; cg = d2; og = d3; row = rbase + 8; }
            fg += __ldg(&bfv[u]); ig += __ldg(&biv[u]);
            cg += __ldg(&bcv[u]); og += __ldg(&bov[u]);
            float ft = sigf(fg), it = sigf(ig);
            float gt = tanhfast(cg), ot = sigf(og);
            size_t idx = (size_t)row * UNITS + u;
            float nc = ft * __ldg(&cin[idx]) + it * gt;
            float nh = ot * tanhfast(nc);
            out[idx] = nh;                                   // new_h
            out[(size_t)BROWS * UNITS + idx] = nc;           // new_c
        }
    }
}

// ============================================================
// kernel_launch — single fused pre-pass launch, then GEMM.
// ============================================================
extern "C" void kernel_launch(void* const* d_in, const int* in_sizes, int n_in,
                              void* d_out, int out_size) {
    const float* x  = (const float*)d_in[0];
    const float* h  = (const float*)d_in[1];
    const float* c  = (const float*)d_in[2];
    const float* Wf = (const float*)d_in[3];
    const float* bf = (const float*)d_in[4];
    const float* Wi = (const float*)d_in[5];
    const float* bi = (const float*)d_in[6];
    const float* Wc = (const float*)d_in[7];
    const float* bc = (const float*)d_in[8];
    const float* Wo = (const float*)d_in[9];
    const float* bo = (const float*)d_in[10];
    float* out = (float*)d_out;

    static bool inited = false;
    if (!inited) {
        cudaFuncSetAttribute(gemm_lstm_kernel,
                             cudaFuncAttributeMaxDynamicSharedMemorySize, SMEM_TOTAL);
        inited = true;
    }

    prepass_kernel<<<PACK_BLOCKS + TRANS_BLOCKS, 256>>>(x, h, Wf, Wi, Wc, Wo);

    int grid = (BROWS / BM) * (NTOT / BN);   // 2048
    gemm_lstm_kernel<<<grid, 256, SMEM_TOTAL>>>(c, bf, bi, bc, bo, out);
}